// round 14
// baseline (speedup 1.0000x reference)
#include <cuda_runtime.h>
#include <cstdint>

#define TSTEPS 2048
#define BATCH  32
#define EDIM   512
#define HDIM   512
#define C4     2048
#define NCTA   128

typedef unsigned long long ull;

__device__ float    g_xp[(size_t)TSTEPS * C4 * BATCH];     // [t][c][b]
__device__ float    g_embT[(size_t)TSTEPS * EDIM * BATCH]; // [t][k][b]
__device__ float    g_h[2][HDIM * BATCH];                  // [col][b]
__device__ unsigned g_grp[8];                              // tree barrier: 16 CTAs/group
__device__ unsigned g_root;

__device__ __forceinline__ ull ffma2(ull a, ull b, ull c) {
    ull d;
    asm("fma.rn.f32x2 %0, %1, %2, %3;" : "=l"(d) : "l"(a), "l"(b), "l"(c));
    return d;
}
__device__ __forceinline__ ull fadd2(ull a, ull b) {
    ull d;
    asm("add.rn.f32x2 %0, %1, %2;" : "=l"(d) : "l"(a), "l"(b));
    return d;
}
__device__ __forceinline__ ull pack2(float lo, float hi) {
    return ((ull)__float_as_uint(hi) << 32) | (ull)__float_as_uint(lo);
}
__device__ __forceinline__ ull dup2(float v) {
    ull d; unsigned u = __float_as_uint(v);
    asm("mov.b64 %0, {%1, %1};" : "=l"(d) : "r"(u));
    return d;
}
__device__ __forceinline__ float hsum2(ull u) {
    return __uint_as_float((unsigned)u) + __uint_as_float((unsigned)(u >> 32));
}
__device__ __forceinline__ float sigf(float x) { return 1.0f / (1.0f + __expf(-x)); }
__device__ __forceinline__ float tanhf_fast(float x) {
    return __fmaf_rn(2.0f, sigf(2.0f * x), -1.0f);
}

// ---------------------------------------------------------------------------
__global__ void k_init() {
    int i = blockIdx.x * blockDim.x + threadIdx.x;
    if (i < 2 * HDIM * BATCH) ((float*)g_h)[i] = 0.0f;
    if (i < 8) g_grp[i] = 0u;
    if (i == 8) g_root = 0u;
}

// ---------------------------------------------------------------------------
// Transpose emb[t][b][k] -> g_embT[t][k][b]. One CTA per t.
// ---------------------------------------------------------------------------
__global__ void __launch_bounds__(256) k_transp(const float* __restrict__ emb) {
    extern __shared__ float tile[];       // [32 b][516] padded
    const int tid = threadIdx.x;
    const int t   = blockIdx.x;
    const float4* src = (const float4*)(emb + (size_t)t * (BATCH * EDIM));
    #pragma unroll
    for (int j = 0; j < 16; j++) {
        int fidx = j * 256 + tid;
        int b  = fidx >> 7;
        int kq = fidx & 127;
        float4 v = src[b * 128 + kq];
        *(float4*)&tile[b * 516 + kq * 4] = v;
    }
    __syncthreads();
    float* dst = g_embT + (size_t)t * (EDIM * BATCH);
    #pragma unroll
    for (int j = 0; j < 16; j++) {
        int oidx = j * 256 + tid;
        int k  = oidx >> 3;
        int bq = oidx & 7;
        float4 v;
        v.x = tile[(bq * 4 + 0) * 516 + k];
        v.y = tile[(bq * 4 + 1) * 516 + k];
        v.z = tile[(bq * 4 + 2) * 516 + k];
        v.w = tile[(bq * 4 + 3) * 516 + k];
        *(float4*)&dst[k * 32 + bq * 4] = v;
    }
}

// ---------------------------------------------------------------------------
// Phase 1: xp[t][c][b] = sum_k embT[t][k][b] * Wx[k][c] + bias[c]
// Thread = 4b x 4c; W undup float4 + dup2-in-regs; A read directly from
// g_embT via coalesced ld.global.nc (L1 serves the 8-warp reuse).
// ---------------------------------------------------------------------------
__global__ void __launch_bounds__(256, 2) k_xproj(
    const float* __restrict__ wxi, const float* __restrict__ wxf,
    const float* __restrict__ wxg, const float* __restrict__ wxo,
    const float* __restrict__ bi,  const float* __restrict__ bf,
    const float* __restrict__ bg,  const float* __restrict__ bo)
{
    extern __shared__ float ws[];        // 2 bufs x [16 k][132] floats

    const int tid  = threadIdx.x;
    const int lane = tid & 31;
    const int wrp  = tid >> 5;           // 0..7
    const int t    = blockIdx.y;
    const int ct   = blockIdx.x;
    const int gate = ct >> 2;
    const int co   = (ct & 3) * 128;

    const float* W  = (gate == 0) ? wxi : (gate == 1) ? wxf : (gate == 2) ? wxg : wxo;
    const float* bs = (gate == 0) ? bi  : (gate == 1) ? bf  : (gate == 2) ? bg  : bo;

    const int b_grp = lane >> 2;         // 0..7 -> b = b_grp*4 .. +3
    const int c_grp = lane & 3;          // 0..3 -> c = wrp*16 + c_grp*4 .. +3

    const float* At = g_embT + (size_t)t * (EDIM * BATCH) + b_grp * 4;

    float4 pre[2];
    #define XLOAD(kc)                                                          \
        _Pragma("unroll")                                                      \
        for (int i = 0; i < 2; i++)                                            \
            pre[i] = *(const float4*)&W[(size_t)((kc) * 16 + (tid >> 5) + 8 * i) * HDIM + co + lane * 4];
    #define XSTORE(buf)                                                        \
        _Pragma("unroll")                                                      \
        for (int i = 0; i < 2; i++)                                            \
            *(float4*)&(buf)[((tid >> 5) + 8 * i) * 132 + lane * 4] = pre[i];

    XLOAD(0);
    XSTORE(ws);
    __syncthreads();

    ull acc[8];
    #pragma unroll
    for (int j = 0; j < 8; j++) acc[j] = 0ull;

    int p = 0;
    for (int kc = 0; kc < 32; kc++) {
        if (kc < 31) { XLOAD(kc + 1); }
        const float* wb = ws + p * 2112;
        #pragma unroll
        for (int k = 0; k < 16; k++) {
            int kg = kc * 16 + k;
            ull a0, a1;
            asm("ld.global.nc.v2.u64 {%0,%1}, [%2];"
                : "=l"(a0), "=l"(a1) : "l"(At + kg * 32));
            float4 wv = *(const float4*)&wb[k * 132 + (wrp * 4 + c_grp) * 4];
            ull w0 = dup2(wv.x), w1 = dup2(wv.y), w2 = dup2(wv.z), w3 = dup2(wv.w);
            acc[0] = ffma2(a0, w0, acc[0]);
            acc[1] = ffma2(a1, w0, acc[1]);
            acc[2] = ffma2(a0, w1, acc[2]);
            acc[3] = ffma2(a1, w1, acc[3]);
            acc[4] = ffma2(a0, w2, acc[4]);
            acc[5] = ffma2(a1, w2, acc[5]);
            acc[6] = ffma2(a0, w3, acc[6]);
            acc[7] = ffma2(a1, w3, acc[7]);
        }
        if (kc < 31) { XSTORE(ws + (p ^ 1) * 2112); }
        __syncthreads();
        p ^= 1;
    }

    float* xp = g_xp + ((size_t)t * C4 + (size_t)gate * 512 + co) * 32;
    #pragma unroll
    for (int j = 0; j < 4; j++) {
        int c = wrp * 16 + c_grp * 4 + j;
        float bv = __ldg(&bs[co + c]);
        ull bd = dup2(bv);
        ulonglong2 o;
        o.x = fadd2(acc[j * 2],     bd);
        o.y = fadd2(acc[j * 2 + 1], bd);
        *(ulonglong2*)&xp[(size_t)c * 32 + b_grp * 4] = o;
    }
    #undef XLOAD
    #undef XSTORE
}

// ---------------------------------------------------------------------------
// Phase 2: persistent recurrence. Pipelined LDG h + undup'd W (float4+dup2)
// + packed reduce + tree barrier. SMEM OFFSETS FIXED (whsf = 4096 ull).
// ---------------------------------------------------------------------------
#define LOADC(kc, A0, A1)                                                  \
    _Pragma("unroll")                                                      \
    for (int k = 0; k < 8; k++) {                                          \
        asm("ld.global.cg.v2.u64 {%0,%1}, [%2];"                           \
            : "=l"(A0[k]), "=l"(A1[k])                                     \
            : "l"(hb + ((kc) * 8 + k) * 32));                              \
    }

#define COMPC(kc, A0, A1)                                                  \
    _Pragma("unroll")                                                      \
    for (int k = 0; k < 8; k++) {                                          \
        float4 wv = *(const float4*)&whsf[(k0 + (kc) * 8 + k) * 16 + c_grp * 4]; \
        ull w0 = dup2(wv.x), w1 = dup2(wv.y), w2 = dup2(wv.z), w3 = dup2(wv.w);  \
        acc[0] = ffma2(A0[k], w0, acc[0]);                                 \
        acc[1] = ffma2(A1[k], w0, acc[1]);                                 \
        acc[2] = ffma2(A0[k], w1, acc[2]);                                 \
        acc[3] = ffma2(A1[k], w1, acc[3]);                                 \
        acc[4] = ffma2(A0[k], w2, acc[4]);                                 \
        acc[5] = ffma2(A1[k], w2, acc[5]);                                 \
        acc[6] = ffma2(A0[k], w3, acc[6]);                                 \
        acc[7] = ffma2(A1[k], w3, acc[7]);                                 \
    }

__global__ void __launch_bounds__(512, 1) k_rec(
    const float* __restrict__ whi, const float* __restrict__ whf,
    const float* __restrict__ whg, const float* __restrict__ who,
    float* __restrict__ out)
{
    extern __shared__ ull sr[];
    float* whsf = (float*)sr;            // [512 k][16 lc] floats = 4096 ull
    ull*   red  = sr + 4096;             // [16 w][16 c x 18]      = 4608 ull
    ull*   sgu  = sr + 8704;             // [16 c][16 bp]          = 256 ull
    float* sgf  = (float*)sgu;
    float* ost  = (float*)(sr + 8960);   // [32 b][4 hu]           = 64 ull
    // total 9024 ull = 72192 B

    const int tid  = threadIdx.x;
    const int lane = tid & 31;
    const int wrp  = tid >> 5;           // 0..15
    const int cta  = blockIdx.x;

    // Stage Wh undup'd: whsf[k*16 + lc] = W[k][cta*4 + (lc&3)], lc = gate*4+hu.
    for (int i = tid; i < 8192; i += 512) {
        int k = i >> 4, lc = i & 15;
        int g = lc >> 2, hu = lc & 3;
        const float* Wp = (g == 0) ? whi : (g == 1) ? whf : (g == 2) ? whg : who;
        whsf[i] = Wp[(size_t)k * HDIM + cta * 4 + hu];
    }
    __syncthreads();

    const int b_grp = lane >> 2;
    const int c_grp = lane & 3;
    const int k0    = wrp * 32;
    const int hu_g  = tid >> 5;          // gate phase (tid<128)
    const int b_g   = tid & 31;
    const int cl_r  = tid >> 4;          // reduce phase (tid<256)
    const int bp_r  = tid & 15;
    float c_state = 0.0f;

    unsigned* grpp  = &g_grp[cta >> 4];
    unsigned* rootp = &g_root;

    for (int t = 0; t < TSTEPS; t++) {
        const int pin = t & 1;
        const float* hb = g_h[pin] + k0 * 32 + b_grp * 4;

        // xp prefetch (consumed in reduce phase ~2K cycles later).
        float2 xv = make_float2(0.f, 0.f);
        if (tid < 256) {
            int g = cl_r >> 2, hu = cl_r & 3;
            xv = __ldcg((const float2*)&g_xp[
                ((size_t)t * C4 + (size_t)(g * 512 + cta * 4 + hu)) * 32 + bp_r * 2]);
        }

        ull acc[8];
        #pragma unroll
        for (int j = 0; j < 8; j++) acc[j] = 0ull;

        // Software-pipelined matmul: chunks of 8 k, distance-1 prefetch.
        {
            ull pa0[8], pa1[8], pb0[8], pb1[8];
            LOADC(0, pa0, pa1);
            LOADC(1, pb0, pb1);
            COMPC(0, pa0, pa1);
            LOADC(2, pa0, pa1);
            COMPC(1, pb0, pb1);
            LOADC(3, pb0, pb1);
            COMPC(2, pa0, pa1);
            COMPC(3, pb0, pb1);
        }

        #pragma unroll
        for (int j = 0; j < 4; j++) {
            ulonglong2 v;
            v.x = acc[j * 2];
            v.y = acc[j * 2 + 1];
            *(ulonglong2*)&red[wrp * 288 + (c_grp * 4 + j) * 18 + b_grp * 2] = v;
        }
        __syncthreads();

        // Parallel packed reduce: 256 threads, one (lc, b-pair) each.
        if (tid < 256) {
            ull v[16];
            #pragma unroll
            for (int w = 0; w < 16; w++)
                v[w] = red[w * 288 + cl_r * 18 + bp_r];
            #pragma unroll
            for (int st = 8; st >= 1; st >>= 1)
                #pragma unroll
                for (int w = 0; w < st; w++) v[w] = fadd2(v[w], v[w + st]);
            sgu[cl_r * 16 + bp_r] = fadd2(v[0], pack2(xv.x, xv.y));
        }
        __syncthreads();

        if (tid < 128) {
            float s0 = sgf[(0 * 4 + hu_g) * 32 + b_g];
            float s1 = sgf[(1 * 4 + hu_g) * 32 + b_g];
            float s2 = sgf[(2 * 4 + hu_g) * 32 + b_g];
            float s3 = sgf[(3 * 4 + hu_g) * 32 + b_g];
            float ig = sigf(s0);
            float fg = sigf(s1);
            float gg = tanhf_fast(s2);
            float og = sigf(s3);
            c_state = fg * c_state + ig * gg;
            float hval = og * tanhf_fast(c_state);

            int col = cta * 4 + hu_g;
            __stcg(&((float*)g_h[pin ^ 1])[col * 32 + b_g], hval);
            ost[b_g * 4 + hu_g] = hval;
        }
        __syncthreads();     // h stores done CTA-wide

        if (t < TSTEPS - 1) {
            if (tid == 0) {
                unsigned old;
                asm volatile("atom.acq_rel.gpu.global.add.u32 %0, [%1], 1;"
                             : "=r"(old) : "l"(grpp) : "memory");
                if (old == 16u * (unsigned)(t + 1) - 1u) {
                    asm volatile("red.release.gpu.global.add.u32 [%0], 1;"
                                 :: "l"(rootp) : "memory");
                }
            }
            if (tid >= 128 && tid < 160) {
                int b = tid - 128;
                float4 o4 = *(const float4*)&ost[b * 4];
                *(float4*)&out[(size_t)t * (BATCH * HDIM) + (size_t)b * HDIM + cta * 4] = o4;
            }
            if (tid == 0) {
                unsigned target = 8u * (unsigned)(t + 1);
                unsigned v;
                do {
                    asm volatile("ld.acquire.gpu.global.u32 %0, [%1];"
                                 : "=r"(v) : "l"(rootp) : "memory");
                } while (v < target);
            }
            __syncthreads();
        } else {
            if (tid >= 128 && tid < 160) {
                int b = tid - 128;
                float4 o4 = *(const float4*)&ost[b * 4];
                *(float4*)&out[(size_t)t * (BATCH * HDIM) + (size_t)b * HDIM + cta * 4] = o4;
            }
        }
    }
}

// ---------------------------------------------------------------------------
extern "C" void kernel_launch(void* const* d_in, const int* in_sizes, int n_in,
                              void* d_out, int out_size) {
    const float* emb = (const float*)d_in[0];
    const float* wxi = (const float*)d_in[1];
    const float* whi = (const float*)d_in[2];
    const float* bi  = (const float*)d_in[3];
    const float* wxf = (const float*)d_in[4];
    const float* whf = (const float*)d_in[5];
    const float* bf  = (const float*)d_in[6];
    const float* wxg = (const float*)d_in[7];
    const float* whg = (const float*)d_in[8];
    const float* bg  = (const float*)d_in[9];
    const float* wxo = (const float*)d_in[10];
    const float* who = (const float*)d_in[11];
    const float* bo  = (const float*)d_in[12];
    float* out = (float*)d_out;

    cudaFuncSetAttribute(k_transp, cudaFuncAttributeMaxDynamicSharedMemorySize, 66048);
    cudaFuncSetAttribute(k_rec,    cudaFuncAttributeMaxDynamicSharedMemorySize, 73728);

    k_transp<<<TSTEPS, 256, 66048>>>(emb);
    k_xproj<<<dim3(16, TSTEPS), 256, 16896>>>(wxi, wxf, wxg, wxo, bi, bf, bg, bo);
    k_init<<<128, 256>>>();
    k_rec<<<NCTA, 512, 72192>>>(whi, whf, whg, who, out);
}

// round 15
// speedup vs baseline: 1.2559x; 1.2559x over previous
#include <cuda_runtime.h>
#include <cstdint>

#define TSTEPS 2048
#define BATCH  32
#define EDIM   512
#define HDIM   512
#define NCTA   128

typedef unsigned long long ull;

__device__ float    g_embT[(size_t)TSTEPS * EDIM * BATCH]; // [t][k][b]
__device__ float    g_h[2][HDIM * BATCH];                  // [col][b]
__device__ unsigned g_grp[8];                              // tree barrier: 16 CTAs/group
__device__ unsigned g_root;

__device__ __forceinline__ ull ffma2(ull a, ull b, ull c) {
    ull d;
    asm("fma.rn.f32x2 %0, %1, %2, %3;" : "=l"(d) : "l"(a), "l"(b), "l"(c));
    return d;
}
__device__ __forceinline__ ull fadd2(ull a, ull b) {
    ull d;
    asm("add.rn.f32x2 %0, %1, %2;" : "=l"(d) : "l"(a), "l"(b));
    return d;
}
__device__ __forceinline__ ull dup2(float v) {
    ull d; unsigned u = __float_as_uint(v);
    asm("mov.b64 %0, {%1, %1};" : "=l"(d) : "r"(u));
    return d;
}
__device__ __forceinline__ float sigf(float x) { return 1.0f / (1.0f + __expf(-x)); }
__device__ __forceinline__ float tanhf_fast(float x) {
    return __fmaf_rn(2.0f, sigf(2.0f * x), -1.0f);
}

// ---------------------------------------------------------------------------
__global__ void k_init() {
    int i = blockIdx.x * blockDim.x + threadIdx.x;
    if (i < 2 * HDIM * BATCH) ((float*)g_h)[i] = 0.0f;
    if (i < 8) g_grp[i] = 0u;
    if (i == 8) g_root = 0u;
}

// ---------------------------------------------------------------------------
// Transpose emb[t][b][k] -> g_embT[t][k][b]. One CTA per t. (Measured-passing.)
// ---------------------------------------------------------------------------
__global__ void __launch_bounds__(256) k_transp(const float* __restrict__ emb) {
    extern __shared__ float tile[];       // [32 b][516] padded
    const int tid = threadIdx.x;
    const int t   = blockIdx.x;
    const float4* src = (const float4*)(emb + (size_t)t * (BATCH * EDIM));
    #pragma unroll
    for (int j = 0; j < 16; j++) {
        int fidx = j * 256 + tid;
        int b  = fidx >> 7;
        int kq = fidx & 127;
        float4 v = src[b * 128 + kq];
        *(float4*)&tile[b * 516 + kq * 4] = v;
    }
    __syncthreads();
    float* dst = g_embT + (size_t)t * (EDIM * BATCH);
    #pragma unroll
    for (int j = 0; j < 16; j++) {
        int oidx = j * 256 + tid;
        int k  = oidx >> 3;
        int bq = oidx & 7;
        float4 v;
        v.x = tile[(bq * 4 + 0) * 516 + k];
        v.y = tile[(bq * 4 + 1) * 516 + k];
        v.z = tile[(bq * 4 + 2) * 516 + k];
        v.w = tile[(bq * 4 + 3) * 516 + k];
        *(float4*)&dst[k * 32 + bq * 4] = v;
    }
}

// ---------------------------------------------------------------------------
// Fused persistent LSTM: per step each CTA computes, for its 16 gate-cols,
//   acc = embT[t] @ WxSlice   (h-independent -> overlaps barrier wait)
//       + h(t)    @ WhSlice   (after barrier)
// then reduce(+bias), gates, h-store, tree-barrier arrive.
// ---------------------------------------------------------------------------
#define LOADC(base, kc, A0, A1)                                            \
    _Pragma("unroll")                                                      \
    for (int k = 0; k < 8; k++) {                                          \
        asm("ld.global.cg.v2.u64 {%0,%1}, [%2];"                           \
            : "=l"(A0[k]), "=l"(A1[k])                                     \
            : "l"((base) + ((kc) * 8 + k) * 32));                          \
    }

#define COMPC(Wt, kc, A0, A1)                                              \
    _Pragma("unroll")                                                      \
    for (int k = 0; k < 8; k++) {                                          \
        float4 wv = *(const float4*)&(Wt)[(k0 + (kc) * 8 + k) * 16 + c_grp * 4]; \
        ull w0 = dup2(wv.x), w1 = dup2(wv.y), w2 = dup2(wv.z), w3 = dup2(wv.w);  \
        acc[0] = ffma2(A0[k], w0, acc[0]);                                 \
        acc[1] = ffma2(A1[k], w0, acc[1]);                                 \
        acc[2] = ffma2(A0[k], w1, acc[2]);                                 \
        acc[3] = ffma2(A1[k], w1, acc[3]);                                 \
        acc[4] = ffma2(A0[k], w2, acc[4]);                                 \
        acc[5] = ffma2(A1[k], w2, acc[5]);                                 \
        acc[6] = ffma2(A0[k], w3, acc[6]);                                 \
        acc[7] = ffma2(A1[k], w3, acc[7]);                                 \
    }

#define MATMUL(base, Wt)                                                   \
    {                                                                      \
        ull pa0[8], pa1[8], pb0[8], pb1[8];                                \
        LOADC(base, 0, pa0, pa1);                                          \
        LOADC(base, 1, pb0, pb1);                                          \
        COMPC(Wt, 0, pa0, pa1);                                            \
        LOADC(base, 2, pa0, pa1);                                          \
        COMPC(Wt, 1, pb0, pb1);                                            \
        LOADC(base, 3, pb0, pb1);                                          \
        COMPC(Wt, 2, pa0, pa1);                                            \
        COMPC(Wt, 3, pb0, pb1);                                            \
    }

__global__ void __launch_bounds__(512, 1) k_rec(
    const float* __restrict__ whi, const float* __restrict__ whf,
    const float* __restrict__ whg, const float* __restrict__ who,
    const float* __restrict__ wxi, const float* __restrict__ wxf,
    const float* __restrict__ wxg, const float* __restrict__ wxo,
    const float* __restrict__ bi,  const float* __restrict__ bf,
    const float* __restrict__ bg,  const float* __restrict__ bo,
    float* __restrict__ out)
{
    extern __shared__ ull sr[];
    float* whsf  = (float*)sr;            // [512 k][16 lc] floats = 4096 ull
    float* wxsf  = (float*)(sr + 4096);   // [512 k][16 lc] floats = 4096 ull
    ull*   red   = sr + 8192;             // [16 w][16 c x 18]      = 4608 ull
    ull*   sgu   = sr + 12800;            // [16 c][16 bp]          = 256 ull
    float* sgf   = (float*)sgu;
    float* ost   = (float*)(sr + 13056);  // [32 b][4 hu]           = 64 ull
    float* sbias = (float*)(sr + 13120);  // [16 lc]                = 8 ull
    // total 13128 ull = 105024 B

    const int tid  = threadIdx.x;
    const int lane = tid & 31;
    const int wrp  = tid >> 5;           // 0..15
    const int cta  = blockIdx.x;

    // Stage Wh + Wx slices undup'd: [k*16 + lc], col = cta*4 + (lc&3).
    for (int i = tid; i < 8192; i += 512) {
        int k = i >> 4, lc = i & 15;
        int g = lc >> 2, hu = lc & 3;
        const float* Wh = (g == 0) ? whi : (g == 1) ? whf : (g == 2) ? whg : who;
        const float* Wx = (g == 0) ? wxi : (g == 1) ? wxf : (g == 2) ? wxg : wxo;
        whsf[i] = Wh[(size_t)k * HDIM + cta * 4 + hu];
        wxsf[i] = Wx[(size_t)k * HDIM + cta * 4 + hu];
    }
    if (tid < 16) {
        int g = tid >> 2, hu = tid & 3;
        const float* bp = (g == 0) ? bi : (g == 1) ? bf : (g == 2) ? bg : bo;
        sbias[tid] = bp[cta * 4 + hu];
    }
    __syncthreads();

    const int b_grp = lane >> 2;
    const int c_grp = lane & 3;
    const int k0    = wrp * 32;
    const int hu_g  = tid >> 5;          // gate phase (tid<128)
    const int b_g   = tid & 31;
    const int cl_r  = tid >> 4;          // reduce phase (tid<256)
    const int bp_r  = tid & 15;
    float c_state = 0.0f;

    unsigned* grpp  = &g_grp[cta >> 4];
    unsigned* rootp = &g_root;

    for (int t = 0; t < TSTEPS; t++) {
        const int pin = t & 1;

        ull acc[8];
        #pragma unroll
        for (int j = 0; j < 8; j++) acc[j] = 0ull;

        // Phase A: input-projection matmul (h-independent). Overlaps the
        // barrier wait: runs while straggler CTAs finish step t-1.
        {
            const float* eb = g_embT + (size_t)t * (EDIM * BATCH) + k0 * 32 + b_grp * 4;
            MATMUL(eb, wxsf);
        }

        // Barrier wait: h(t) published by all CTAs (arrive was at end of t-1).
        if (t > 0) {
            if (tid == 0) {
                unsigned target = 8u * (unsigned)t;
                unsigned v;
                do {
                    asm volatile("ld.acquire.gpu.global.u32 %0, [%1];"
                                 : "=r"(v) : "l"(rootp) : "memory");
                } while (v < target);
            }
            __syncthreads();
        }

        // Phase B: recurrent matmul.
        {
            const float* hb = g_h[pin] + k0 * 32 + b_grp * 4;
            MATMUL(hb, whsf);
        }

        #pragma unroll
        for (int j = 0; j < 4; j++) {
            ulonglong2 v;
            v.x = acc[j * 2];
            v.y = acc[j * 2 + 1];
            *(ulonglong2*)&red[wrp * 288 + (c_grp * 4 + j) * 18 + b_grp * 2] = v;
        }
        __syncthreads();

        // Parallel packed reduce + bias: 256 threads, one (lc, b-pair) each.
        if (tid < 256) {
            ull v[16];
            #pragma unroll
            for (int w = 0; w < 16; w++)
                v[w] = red[w * 288 + cl_r * 18 + bp_r];
            #pragma unroll
            for (int st = 8; st >= 1; st >>= 1)
                #pragma unroll
                for (int w = 0; w < st; w++) v[w] = fadd2(v[w], v[w + st]);
            sgu[cl_r * 16 + bp_r] = fadd2(v[0], dup2(sbias[cl_r]));
        }
        __syncthreads();

        if (tid < 128) {
            float s0 = sgf[(0 * 4 + hu_g) * 32 + b_g];
            float s1 = sgf[(1 * 4 + hu_g) * 32 + b_g];
            float s2 = sgf[(2 * 4 + hu_g) * 32 + b_g];
            float s3 = sgf[(3 * 4 + hu_g) * 32 + b_g];
            float ig = sigf(s0);
            float fg = sigf(s1);
            float gg = tanhf_fast(s2);
            float og = sigf(s3);
            c_state = fg * c_state + ig * gg;
            float hval = og * tanhf_fast(c_state);

            int col = cta * 4 + hu_g;
            __stcg(&((float*)g_h[pin ^ 1])[col * 32 + b_g], hval);
            ost[b_g * 4 + hu_g] = hval;
        }
        __syncthreads();     // h stores done CTA-wide

        // Arrive (no wait here — wait happens after next step's Phase A).
        if (t < TSTEPS - 1 && tid == 0) {
            unsigned old;
            asm volatile("atom.acq_rel.gpu.global.add.u32 %0, [%1], 1;"
                         : "=r"(old) : "l"(grpp) : "memory");
            if (old == 16u * (unsigned)(t + 1) - 1u) {
                asm volatile("red.release.gpu.global.add.u32 [%0], 1;"
                             :: "l"(rootp) : "memory");
            }
        }

        // out store overlaps other CTAs' arrivals.
        if (tid >= 128 && tid < 160) {
            int b = tid - 128;
            float4 o4 = *(const float4*)&ost[b * 4];
            *(float4*)&out[(size_t)t * (BATCH * HDIM) + (size_t)b * HDIM + cta * 4] = o4;
        }
    }
}

// ---------------------------------------------------------------------------
extern "C" void kernel_launch(void* const* d_in, const int* in_sizes, int n_in,
                              void* d_out, int out_size) {
    const float* emb = (const float*)d_in[0];
    const float* wxi = (const float*)d_in[1];
    const float* whi = (const float*)d_in[2];
    const float* bi  = (const float*)d_in[3];
    const float* wxf = (const float*)d_in[4];
    const float* whf = (const float*)d_in[5];
    const float* bf  = (const float*)d_in[6];
    const float* wxg = (const float*)d_in[7];
    const float* whg = (const float*)d_in[8];
    const float* bg  = (const float*)d_in[9];
    const float* wxo = (const float*)d_in[10];
    const float* who = (const float*)d_in[11];
    const float* bo  = (const float*)d_in[12];
    float* out = (float*)d_out;

    cudaFuncSetAttribute(k_transp, cudaFuncAttributeMaxDynamicSharedMemorySize, 66048);
    cudaFuncSetAttribute(k_rec,    cudaFuncAttributeMaxDynamicSharedMemorySize, 105472);

    k_transp<<<TSTEPS, 256, 66048>>>(emb);
    k_init<<<128, 256>>>();
    k_rec<<<NCTA, 512, 105024>>>(whi, whf, whg, who,
                                 wxi, wxf, wxg, wxo,
                                 bi, bf, bg, bo, out);
}